// round 13
// baseline (speedup 1.0000x reference)
#include <cuda_runtime.h>
#include <math.h>

#define N_NODES 10000
#define C_IN 128
#define D_OUT 20
#define KNN_K 16
#define FULLM 0xffffffffu

#define ETPB 256                   // emb knn threads per block
#define EWPB (ETPB / 32)           // 8 queries per block
#define PTPB 512                   // pos knn threads per block
#define PWPB (PTPB / 32)           // 16 queries per block
#define TC 512                     // candidate tile

// ---------------- scratch (static device globals; no allocs) ----------------
__device__ float g_h[N_NODES * D_OUT];
__device__ float g_emb[N_NODES * D_OUT];
__device__ float g_embn[N_NODES * D_OUT];
__device__ float g_sqe[N_NODES];
__device__ float4 g_pos4[N_NODES];         // {x, y, z, sq}
__device__ float g_mu[D_OUT];
__device__ float g_rinv[D_OUT];
__device__ int   g_idx_emb[N_NODES * KNN_K];
__device__ int   g_idx_pos[N_NODES * KNN_K];

__device__ __forceinline__ float inf_f() { return __int_as_float(0x7f800000); }

// ---------------- 1) linear: h = x @ W + b ----------------
__global__ void k_linear(const float* __restrict__ x, const float* __restrict__ W,
                         const float* __restrict__ b) {
    int t = blockIdx.x * blockDim.x + threadIdx.x;
    if (t >= N_NODES * D_OUT) return;
    int i = t / D_OUT;
    int d = t % D_OUT;
    const float* xr = x + (size_t)i * C_IN;
    float acc = 0.f;
#pragma unroll 8
    for (int c = 0; c < C_IN; ++c) acc = fmaf(xr[c], W[c * D_OUT + d], acc);
    g_h[t] = acc + b[d];
}

// ---------------- 2) batchnorm stats (deterministic) ----------------
__global__ void k_stats() {
    __shared__ float ss[256];
    __shared__ float sq[256];
    int d = blockIdx.x;
    int tid = threadIdx.x;
    float s = 0.f, q = 0.f;
    for (int i = tid; i < N_NODES; i += 256) {
        float v = g_h[i * D_OUT + d];
        s += v;
        q = fmaf(v, v, q);
    }
    ss[tid] = s; sq[tid] = q;
    __syncthreads();
    for (int o = 128; o > 0; o >>= 1) {
        if (tid < o) { ss[tid] += ss[tid + o]; sq[tid] += sq[tid + o]; }
        __syncthreads();
    }
    if (tid == 0) {
        float mu = ss[0] / (float)N_NODES;
        float var = sq[0] / (float)N_NODES - mu * mu;
        g_mu[d] = mu;
        g_rinv[d] = 1.f / sqrtf(var + 1e-5f);
    }
}

// ---------------- 3) fused: emb = relu(bn(h)); embn; sq norms; pos4 ----------------
__global__ void k_emb_sqn(const float* __restrict__ noise, const float* __restrict__ gamma,
                          const float* __restrict__ beta, const float* __restrict__ pos) {
    int i = blockIdx.x * blockDim.x + threadIdx.x;
    if (i >= N_NODES) return;
    float s = 0.f;
#pragma unroll
    for (int d = 0; d < D_OUT; ++d) {
        int t = i * D_OUT + d;
        float e = (g_h[t] - g_mu[d]) * g_rinv[d] * gamma[d] + beta[d];
        e = fmaxf(e, 0.f);
        g_emb[t] = e;
        g_embn[t] = e + noise[t] * 1e-4f;
        s = fmaf(e, e, s);
    }
    g_sqe[i] = s;
    float p0 = pos[i * 3 + 0], p1 = pos[i * 3 + 1], p2 = pos[i * 3 + 2];
    float s0 = __fmul_rn(p0, p0);
    float s1 = __fmul_rn(p1, p1);
    float s2 = __fmul_rn(p2, p2);
    float psq = __fadd_rn(__fadd_rn(s0, s1), s2);
    g_pos4[i] = make_float4(p0, p1, p2, psq);
}

// ---------------- warp-distributed top-k ----------------
__device__ __forceinline__ bool lt_pair(float d2a, int ia, float d2b, int ib) {
    return (d2a < d2b) || (d2a == d2b && ia < ib);
}

__device__ __forceinline__ void warp_hits(unsigned mask, float d2, int jj, int lane,
                                          float& kd, int& ki, float& kth_d, int& kth_i) {
    while (mask) {
        int src = __ffs(mask) - 1;
        mask &= mask - 1;
        float dn = __shfl_sync(FULLM, d2, src);
        int   in = __shfl_sync(FULLM, jj, src);
        if (lt_pair(dn, in, kth_d, kth_i)) {
            bool p = lt_pair(dn, in, kd, ki);
            unsigned pm = __ballot_sync(FULLM, p);
            int pos = __ffs(pm) - 1;
            float kdu = __shfl_up_sync(FULLM, kd, 1);
            int   kiu = __shfl_up_sync(FULLM, ki, 1);
            if (p) {
                kd = (lane == pos) ? dn : kdu;
                ki = (lane == pos) ? in : kiu;
            }
            kth_d = __shfl_sync(FULLM, kd, 15);
            kth_i = __shfl_sync(FULLM, ki, 15);
        }
    }
}

// single-candidate selection (exact pre-filter ballot + distributed insert)
__device__ __forceinline__ void sel1(float d2v, int jv, int lane,
                                     float& kd, int& ki, float& kth_d, int& kth_i) {
    unsigned m = __ballot_sync(FULLM, lt_pair(d2v, jv, kth_d, kth_i));
    if (m) warp_hits(m, d2v, jv, lane, kd, ki, kth_d, kth_i);
}

// 4-candidate selection with one any-hit ballot on the (common) no-hit path.
// Exactness: predicates are the exact lexicographic pre-filter; on a hit we
// fall back to per-candidate ballots recomputed against the current kth, and
// warp_hits rechecks each value against the updated kth.
__device__ __forceinline__ void sel4(float d0, int j0, float d1, int j1,
                                     float d2, int j2, float d3, int j3, int lane,
                                     float& kd, int& ki, float& kth_d, int& kth_i) {
    bool h0 = lt_pair(d0, j0, kth_d, kth_i);
    bool h1 = lt_pair(d1, j1, kth_d, kth_i);
    bool h2 = lt_pair(d2, j2, kth_d, kth_i);
    bool h3 = lt_pair(d3, j3, kth_d, kth_i);
    unsigned many = __ballot_sync(FULLM, h0 | h1 | h2 | h3);
    if (many) {
        sel1(d0, j0, lane, kd, ki, kth_d, kth_i);
        sel1(d1, j1, lane, kd, ki, kth_d, kth_i);
        sel1(d2, j2, lane, kd, ki, kth_d, kth_i);
        sel1(d3, j3, lane, kd, ki, kth_d, kth_i);
    }
}

// ---------------- 4) emb knn ----------------
// Dense 20-float rows: LDS.128 over 8-lane phases hits banks
// {0,20,8,28,16,4,24,12} -> conflict-free.
template <bool HASQ>
__device__ __forceinline__ void emb_group(
    int base, int c0, int lane, int q,
    const float (&qv)[D_OUT], float qsq,
    const float* s_feat, const float* s_sq,
    float& kd, int& ki, float& kth_d, int& kth_i) {
    const int ca = c0 + lane;
    const float4* r0 = (const float4*)&s_feat[ca * D_OUT];
    const float4* r1 = (const float4*)&s_feat[(ca + 32) * D_OUT];
    const float4* r2 = (const float4*)&s_feat[(ca + 64) * D_OUT];
    const float4* r3 = (const float4*)&s_feat[(ca + 96) * D_OUT];
    float a0 = 0.f, a1 = 0.f, a2 = 0.f, a3 = 0.f;
#pragma unroll
    for (int kk = 0; kk < D_OUT / 4; ++kk) {
        float4 v0 = r0[kk], v1 = r1[kk], v2 = r2[kk], v3 = r3[kk];
        float q0 = qv[4 * kk + 0], q1 = qv[4 * kk + 1];
        float q2 = qv[4 * kk + 2], q3 = qv[4 * kk + 3];
        a0 = fmaf(q0, v0.x, a0); a0 = fmaf(q1, v0.y, a0);
        a0 = fmaf(q2, v0.z, a0); a0 = fmaf(q3, v0.w, a0);
        a1 = fmaf(q0, v1.x, a1); a1 = fmaf(q1, v1.y, a1);
        a1 = fmaf(q2, v1.z, a1); a1 = fmaf(q3, v1.w, a1);
        a2 = fmaf(q0, v2.x, a2); a2 = fmaf(q1, v2.y, a2);
        a2 = fmaf(q2, v2.z, a2); a2 = fmaf(q3, v2.w, a2);
        a3 = fmaf(q0, v3.x, a3); a3 = fmaf(q1, v3.y, a3);
        a3 = fmaf(q2, v3.z, a3); a3 = fmaf(q3, v3.w, a3);
    }
    int j0 = base + ca, j1 = j0 + 32, j2 = j0 + 64, j3 = j0 + 96;
    float d0 = fmaf(-2.f, a0, qsq + s_sq[ca]);
    float d1 = fmaf(-2.f, a1, qsq + s_sq[ca + 32]);
    float d2 = fmaf(-2.f, a2, qsq + s_sq[ca + 64]);
    float d3 = fmaf(-2.f, a3, qsq + s_sq[ca + 96]);
    if (HASQ) {
        if (j0 == q) { d0 = inf_f(); j0 = 0x7fffffff; }
        if (j1 == q) { d1 = inf_f(); j1 = 0x7fffffff; }
        if (j2 == q) { d2 = inf_f(); j2 = 0x7fffffff; }
        if (j3 == q) { d3 = inf_f(); j3 = 0x7fffffff; }
    }
    sel4(d0, j0, d1, j1, d2, j2, d3, j3, lane, kd, ki, kth_d, kth_i);
}

__global__ void __launch_bounds__(ETPB, 3) k_knn_emb(const float* __restrict__ feat,
                                                     const float* __restrict__ sqn,
                                                     int* __restrict__ out_idx) {
    __shared__ float s_feat[TC * D_OUT];   // 40 KB dense
    __shared__ float s_sq[TC];
    const int lane = threadIdx.x & 31;
    const int wid = threadIdx.x >> 5;
    const int q = blockIdx.x * EWPB + wid;   // 1250*8 == 10000: always valid

    float qv[D_OUT];
#pragma unroll
    for (int d = 0; d < D_OUT; ++d) qv[d] = feat[(size_t)q * D_OUT + d];
    const float qsq = sqn[q];

    float kd = inf_f();  int ki = 0x7fffffff;
    float kth_d = inf_f(); int kth_i = 0x7fffffff;

    for (int base = 0; base < N_NODES; base += TC) {
        const int cnt = min(TC, N_NODES - base);
        __syncthreads();
        {
            const float4* src4 = (const float4*)(feat + (size_t)base * D_OUT);
            float4* dst4 = (float4*)s_feat;
            const int n4 = (cnt * D_OUT) / 4;
            for (int idx = threadIdx.x; idx < n4; idx += ETPB)
                dst4[idx] = src4[idx];
        }
        for (int idx = threadIdx.x; idx < cnt; idx += ETPB)
            s_sq[idx] = sqn[base + idx];
        __syncthreads();

        if (cnt == TC) {
            const bool hasq = (q >= base) && (q < base + TC);   // warp-uniform
            if (hasq) {
                for (int c0 = 0; c0 < TC; c0 += 128)
                    emb_group<true>(base, c0, lane, q, qv, qsq, s_feat, s_sq,
                                    kd, ki, kth_d, kth_i);
            } else {
                for (int c0 = 0; c0 < TC; c0 += 128)
                    emb_group<false>(base, c0, lane, q, qv, qsq, s_feat, s_sq,
                                     kd, ki, kth_d, kth_i);
            }
        } else {
            // tail tile: guarded, 1 candidate per lane
            for (int c0 = 0; c0 < cnt; c0 += 32) {
                const int ca = c0 + lane;
                const bool bad = (ca >= cnt);
                const int cs = bad ? 0 : ca;
                int j = base + cs;
                const float4* r = (const float4*)&s_feat[cs * D_OUT];
                float a = 0.f;
#pragma unroll
                for (int kk = 0; kk < D_OUT / 4; ++kk) {
                    float4 v = r[kk];
                    a = fmaf(qv[4 * kk + 0], v.x, a);
                    a = fmaf(qv[4 * kk + 1], v.y, a);
                    a = fmaf(qv[4 * kk + 2], v.z, a);
                    a = fmaf(qv[4 * kk + 3], v.w, a);
                }
                float d2v = fmaf(-2.f, a, qsq + s_sq[cs]);
                if (bad || j == q) { d2v = inf_f(); j = 0x7fffffff; }
                sel1(d2v, j, lane, kd, ki, kth_d, kth_i);
            }
        }
    }
    if (lane < KNN_K) out_idx[q * KNN_K + lane] = ki;
}

// ---------------- 5) pos knn ----------------
template <bool HASQ>
__device__ __forceinline__ void pos_group(
    int base, int c0, int lane, int q, float4 qp,
    const float4* s_p,
    float& kd, int& ki, float& kth_d, int& kth_i) {
    const int ca = c0 + lane;
    const float4 v0 = s_p[ca];
    const float4 v1 = s_p[ca + 32];
    const float4 v2 = s_p[ca + 64];
    const float4 v3 = s_p[ca + 96];
    float a0 = fmaf(qp.x, v0.x, 0.f); a0 = fmaf(qp.y, v0.y, a0); a0 = fmaf(qp.z, v0.z, a0);
    float a1 = fmaf(qp.x, v1.x, 0.f); a1 = fmaf(qp.y, v1.y, a1); a1 = fmaf(qp.z, v1.z, a1);
    float a2 = fmaf(qp.x, v2.x, 0.f); a2 = fmaf(qp.y, v2.y, a2); a2 = fmaf(qp.z, v2.z, a2);
    float a3 = fmaf(qp.x, v3.x, 0.f); a3 = fmaf(qp.y, v3.y, a3); a3 = fmaf(qp.z, v3.z, a3);
    float d0 = __fadd_rn(__fadd_rn(qp.w, v0.w), -__fmul_rn(2.f, a0));
    float d1 = __fadd_rn(__fadd_rn(qp.w, v1.w), -__fmul_rn(2.f, a1));
    float d2 = __fadd_rn(__fadd_rn(qp.w, v2.w), -__fmul_rn(2.f, a2));
    float d3 = __fadd_rn(__fadd_rn(qp.w, v3.w), -__fmul_rn(2.f, a3));
    int j0 = base + ca, j1 = j0 + 32, j2 = j0 + 64, j3 = j0 + 96;
    if (HASQ) {
        if (j0 == q) { d0 = inf_f(); j0 = 0x7fffffff; }
        if (j1 == q) { d1 = inf_f(); j1 = 0x7fffffff; }
        if (j2 == q) { d2 = inf_f(); j2 = 0x7fffffff; }
        if (j3 == q) { d3 = inf_f(); j3 = 0x7fffffff; }
    }
    sel4(d0, j0, d1, j1, d2, j2, d3, j3, lane, kd, ki, kth_d, kth_i);
}

__global__ void __launch_bounds__(PTPB) k_knn_pos(const float4* __restrict__ p4,
                                                  int* __restrict__ out_idx) {
    __shared__ float4 s_p[TC];
    const int lane = threadIdx.x & 31;
    const int wid = threadIdx.x >> 5;
    const int q = blockIdx.x * PWPB + wid;   // 625*16 == 10000

    const float4 qp = p4[q];

    float kd = inf_f();  int ki = 0x7fffffff;
    float kth_d = inf_f(); int kth_i = 0x7fffffff;

    for (int base = 0; base < N_NODES; base += TC) {
        const int cnt = min(TC, N_NODES - base);
        __syncthreads();
        for (int idx = threadIdx.x; idx < cnt; idx += PTPB)
            s_p[idx] = p4[base + idx];
        __syncthreads();

        if (cnt == TC) {
            const bool hasq = (q >= base) && (q < base + TC);
            if (hasq) {
                for (int c0 = 0; c0 < TC; c0 += 128)
                    pos_group<true>(base, c0, lane, q, qp, s_p, kd, ki, kth_d, kth_i);
            } else {
                for (int c0 = 0; c0 < TC; c0 += 128)
                    pos_group<false>(base, c0, lane, q, qp, s_p, kd, ki, kth_d, kth_i);
            }
        } else {
            for (int c0 = 0; c0 < cnt; c0 += 32) {
                const int ca = c0 + lane;
                const bool bad = (ca >= cnt);
                const int cs = bad ? 0 : ca;
                int j = base + cs;
                const float4 v = s_p[cs];
                float a = fmaf(qp.x, v.x, 0.f);
                a = fmaf(qp.y, v.y, a);
                a = fmaf(qp.z, v.z, a);
                float d2v = __fadd_rn(__fadd_rn(qp.w, v.w), -__fmul_rn(2.f, a));
                if (bad || j == q) { d2v = inf_f(); j = 0x7fffffff; }
                sel1(d2v, j, lane, kd, ki, kth_d, kth_i);
            }
        }
    }
    if (lane < KNN_K) out_idx[q * KNN_K + lane] = ki;
}

// ---------------- 6) epilogue ----------------
__global__ void k_final(const float* __restrict__ tptr, float* __restrict__ out) {
    const int NK = N_NODES * KNN_K;
    int e = blockIdx.x * blockDim.x + threadIdx.x;
    if (e >= NK) return;
    int i = e / KNN_K;
    int src = g_idx_emb[e];
    float s = 0.f;
#pragma unroll
    for (int d = 0; d < D_OUT; ++d) {
        float df = g_embn[src * D_OUT + d] - g_embn[i * D_OUT + d];
        s = fmaf(df, df, s);
    }
    float dist = sqrtf(s);
    float p = expf(-tptr[0] * dist);
    float fi = (float)i;
    float fs = (float)src;

    out[e] = p;
    out[NK + e] = p;
    out[2 * NK + e] = fi;
    out[3 * NK + e] = fs;
    out[4 * NK + e] = fi;
    out[5 * NK + e] = fs;
    out[6 * NK + e] = (float)g_idx_pos[e];
    out[7 * NK + e] = fi;
    out[8 * NK + e] = fi;
}

// ---------------- launch ----------------
extern "C" void kernel_launch(void* const* d_in, const int* in_sizes, int n_in,
                              void* d_out, int out_size) {
    const float* x     = (const float*)d_in[0];
    const float* pos   = (const float*)d_in[1];
    const float* noise = (const float*)d_in[2];
    const float* W     = (const float*)d_in[3];
    const float* b     = (const float*)d_in[4];
    const float* gamma = (const float*)d_in[5];
    const float* beta  = (const float*)d_in[6];
    const float* t     = (const float*)d_in[7];
    float* out = (float*)d_out;

    int nd = N_NODES * D_OUT;
    k_linear<<<(nd + 255) / 256, 256>>>(x, W, b);
    k_stats<<<D_OUT, 256>>>();
    k_emb_sqn<<<(N_NODES + 255) / 256, 256>>>(noise, gamma, beta, pos);

    int* d_idx_emb; cudaGetSymbolAddress((void**)&d_idx_emb, g_idx_emb);
    int* d_idx_pos; cudaGetSymbolAddress((void**)&d_idx_pos, g_idx_pos);
    float* d_emb;   cudaGetSymbolAddress((void**)&d_emb, g_emb);
    float* d_sqe;   cudaGetSymbolAddress((void**)&d_sqe, g_sqe);
    float4* d_pos4; cudaGetSymbolAddress((void**)&d_pos4, g_pos4);

    k_knn_emb<<<N_NODES / EWPB, ETPB>>>(d_emb, d_sqe, d_idx_emb);   // 4th launch -> profiled
    k_knn_pos<<<N_NODES / PWPB, PTPB>>>(d_pos4, d_idx_pos);

    const int NK = N_NODES * KNN_K;
    k_final<<<(NK + 255) / 256, 256>>>(t, out);
    (void)in_sizes; (void)n_in; (void)out_size;
}

// round 15
// speedup vs baseline: 1.1467x; 1.1467x over previous
#include <cuda_runtime.h>
#include <math.h>

#define N_NODES 10000
#define C_IN 128
#define D_OUT 20
#define KNN_K 16
#define FULLM 0xffffffffu

#define ETPB 256                   // emb knn threads per block
#define EQPB ((ETPB / 32) * 2)     // 16 queries per block (2 per warp)
#define PTPB 256                   // pos knn threads per block
#define PQPB ((PTPB / 32) * 2)     // 16 queries per block
#define TC 512                     // candidate tile

// ---------------- scratch (static device globals; no allocs) ----------------
__device__ float g_h[N_NODES * D_OUT];
__device__ float g_emb[N_NODES * D_OUT];
__device__ float g_embn[N_NODES * D_OUT];
__device__ float g_sqe[N_NODES];
__device__ float4 g_pos4[N_NODES];         // {x, y, z, sq}
__device__ float g_mu[D_OUT];
__device__ float g_rinv[D_OUT];
__device__ int   g_idx_emb[N_NODES * KNN_K];
__device__ int   g_idx_pos[N_NODES * KNN_K];

__device__ __forceinline__ float inf_f() { return __int_as_float(0x7f800000); }

// ---------------- 1) linear: h = x @ W + b ----------------
__global__ void k_linear(const float* __restrict__ x, const float* __restrict__ W,
                         const float* __restrict__ b) {
    int t = blockIdx.x * blockDim.x + threadIdx.x;
    if (t >= N_NODES * D_OUT) return;
    int i = t / D_OUT;
    int d = t % D_OUT;
    const float* xr = x + (size_t)i * C_IN;
    float acc = 0.f;
#pragma unroll 8
    for (int c = 0; c < C_IN; ++c) acc = fmaf(xr[c], W[c * D_OUT + d], acc);
    g_h[t] = acc + b[d];
}

// ---------------- 2) batchnorm stats (deterministic) ----------------
__global__ void k_stats() {
    __shared__ float ss[256];
    __shared__ float sq[256];
    int d = blockIdx.x;
    int tid = threadIdx.x;
    float s = 0.f, q = 0.f;
    for (int i = tid; i < N_NODES; i += 256) {
        float v = g_h[i * D_OUT + d];
        s += v;
        q = fmaf(v, v, q);
    }
    ss[tid] = s; sq[tid] = q;
    __syncthreads();
    for (int o = 128; o > 0; o >>= 1) {
        if (tid < o) { ss[tid] += ss[tid + o]; sq[tid] += sq[tid + o]; }
        __syncthreads();
    }
    if (tid == 0) {
        float mu = ss[0] / (float)N_NODES;
        float var = sq[0] / (float)N_NODES - mu * mu;
        g_mu[d] = mu;
        g_rinv[d] = 1.f / sqrtf(var + 1e-5f);
    }
}

// ---------------- 3) fused: emb = relu(bn(h)); embn; sq norms; pos4 ----------------
__global__ void k_emb_sqn(const float* __restrict__ noise, const float* __restrict__ gamma,
                          const float* __restrict__ beta, const float* __restrict__ pos) {
    int i = blockIdx.x * blockDim.x + threadIdx.x;
    if (i >= N_NODES) return;
    float s = 0.f;
#pragma unroll
    for (int d = 0; d < D_OUT; ++d) {
        int t = i * D_OUT + d;
        float e = (g_h[t] - g_mu[d]) * g_rinv[d] * gamma[d] + beta[d];
        e = fmaxf(e, 0.f);
        g_emb[t] = e;
        g_embn[t] = e + noise[t] * 1e-4f;
        s = fmaf(e, e, s);
    }
    g_sqe[i] = s;
    float p0 = pos[i * 3 + 0], p1 = pos[i * 3 + 1], p2 = pos[i * 3 + 2];
    float s0 = __fmul_rn(p0, p0);
    float s1 = __fmul_rn(p1, p1);
    float s2 = __fmul_rn(p2, p2);
    float psq = __fadd_rn(__fadd_rn(s0, s1), s2);
    g_pos4[i] = make_float4(p0, p1, p2, psq);
}

// ---------------- paired warp-distributed top-k ----------------
// A warp serves TWO queries: even lanes hold query-0's list, odd lanes
// query-1's. Rank r of query p lives at lane 2r+p (ascending by exact
// (d2, idx) lexicographic order); kth = rank 15 at lane 30|p. Insertion is a
// stride-2 shfl shift within the parity class. All sync ops execute in all 32
// lanes; branches guard on ballot results (warp-uniform).
__device__ __forceinline__ bool lt_pair(float d2a, int ia, float d2b, int ib) {
    return (d2a < d2b) || (d2a == d2b && ia < ib);
}

__device__ __forceinline__ void warp_hits_pair(unsigned mask, float d2, int jj, int lane,
                                               float& kd, int& ki, float& kth_d, int& kth_i) {
    while (mask) {
        int src = __ffs(mask) - 1;
        mask &= mask - 1;
        float dn = __shfl_sync(FULLM, d2, src);
        int   in = __shfl_sync(FULLM, jj, src);
        int par = src & 1;
        // beaten suffix of the same-parity list (empty if dn no longer beats kth)
        bool p = ((lane & 1) == par) && lt_pair(dn, in, kd, ki);
        unsigned pm = __ballot_sync(FULLM, p);
        if (pm) {
            int pos = __ffs(pm) - 1;          // insertion lane (lowest beaten rank)
            float kdu = __shfl_up_sync(FULLM, kd, 2);
            int   kiu = __shfl_up_sync(FULLM, ki, 2);
            if (p) {
                kd = (lane == pos) ? dn : kdu;
                ki = (lane == pos) ? in : kiu;
            }
            kth_d = __shfl_sync(FULLM, kd, 30 | (lane & 1));
            kth_i = __shfl_sync(FULLM, ki, 30 | (lane & 1));
        }
    }
}

// single-candidate-slot selection: exact per-lane pre-filter vs own parity's
// kth, then distributed insert with recheck (insert-order independent).
__device__ __forceinline__ void sel1p(float d2v, int jv, int lane,
                                      float& kd, int& ki, float& kth_d, int& kth_i) {
    unsigned m = __ballot_sync(FULLM, lt_pair(d2v, jv, kth_d, kth_i));
    if (m) warp_hits_pair(m, d2v, jv, lane, kd, ki, kth_d, kth_i);
}

// ---------------- 4) emb knn: paired queries, 4-cand ILP ----------------
// Adjacent lanes (2m, 2m+1) read the SAME candidate row (address dedup /
// broadcast on the smem crossbar) but dot it against different queries.
// Dense 20-float rows stay conflict-free: unique rows per 8-lane phase are 4
// consecutive candidates -> bank groups disjoint.
template <bool HASQ>
__device__ __forceinline__ void emb_group_p(
    int base, int c0, int lane, int qown,
    const float (&qv)[D_OUT], float qsq,
    const float* s_feat, const float* s_sq,
    float& kd, int& ki, float& kth_d, int& kth_i) {
    const int cb = c0 + (lane >> 1);          // 16 distinct cands per 32 lanes
    const float4* r0 = (const float4*)&s_feat[cb * D_OUT];
    const float4* r1 = (const float4*)&s_feat[(cb + 16) * D_OUT];
    const float4* r2 = (const float4*)&s_feat[(cb + 32) * D_OUT];
    const float4* r3 = (const float4*)&s_feat[(cb + 48) * D_OUT];
    float a0 = 0.f, a1 = 0.f, a2 = 0.f, a3 = 0.f;
#pragma unroll
    for (int kk = 0; kk < D_OUT / 4; ++kk) {
        float4 v0 = r0[kk], v1 = r1[kk], v2 = r2[kk], v3 = r3[kk];
        float q0 = qv[4 * kk + 0], q1 = qv[4 * kk + 1];
        float q2 = qv[4 * kk + 2], q3 = qv[4 * kk + 3];
        a0 = fmaf(q0, v0.x, a0); a0 = fmaf(q1, v0.y, a0);
        a0 = fmaf(q2, v0.z, a0); a0 = fmaf(q3, v0.w, a0);
        a1 = fmaf(q0, v1.x, a1); a1 = fmaf(q1, v1.y, a1);
        a1 = fmaf(q2, v1.z, a1); a1 = fmaf(q3, v1.w, a1);
        a2 = fmaf(q0, v2.x, a2); a2 = fmaf(q1, v2.y, a2);
        a2 = fmaf(q2, v2.z, a2); a2 = fmaf(q3, v2.w, a2);
        a3 = fmaf(q0, v3.x, a3); a3 = fmaf(q1, v3.y, a3);
        a3 = fmaf(q2, v3.z, a3); a3 = fmaf(q3, v3.w, a3);
    }
    int j0 = base + cb, j1 = j0 + 16, j2 = j0 + 32, j3 = j0 + 48;
    float d0 = fmaf(-2.f, a0, qsq + s_sq[cb]);
    float d1 = fmaf(-2.f, a1, qsq + s_sq[cb + 16]);
    float d2 = fmaf(-2.f, a2, qsq + s_sq[cb + 32]);
    float d3 = fmaf(-2.f, a3, qsq + s_sq[cb + 48]);
    if (HASQ) {
        if (j0 == qown) { d0 = inf_f(); j0 = 0x7fffffff; }
        if (j1 == qown) { d1 = inf_f(); j1 = 0x7fffffff; }
        if (j2 == qown) { d2 = inf_f(); j2 = 0x7fffffff; }
        if (j3 == qown) { d3 = inf_f(); j3 = 0x7fffffff; }
    }
    sel1p(d0, j0, lane, kd, ki, kth_d, kth_i);
    sel1p(d1, j1, lane, kd, ki, kth_d, kth_i);
    sel1p(d2, j2, lane, kd, ki, kth_d, kth_i);
    sel1p(d3, j3, lane, kd, ki, kth_d, kth_i);
}

__global__ void __launch_bounds__(ETPB, 3) k_knn_emb(const float* __restrict__ feat,
                                                     const float* __restrict__ sqn,
                                                     int* __restrict__ out_idx) {
    __shared__ float s_feat[TC * D_OUT];   // 40 KB dense
    __shared__ float s_sq[TC];
    const int lane = threadIdx.x & 31;
    const int wid = threadIdx.x >> 5;
    const int qbase = blockIdx.x * EQPB + wid * 2;   // 625*16 == 10000
    const int qown = qbase + (lane & 1);             // this lane's query

    float qv[D_OUT];
#pragma unroll
    for (int d = 0; d < D_OUT; ++d) qv[d] = feat[(size_t)qown * D_OUT + d];
    const float qsq = sqn[qown];

    float kd = inf_f();  int ki = 0x7fffffff;
    float kth_d = inf_f(); int kth_i = 0x7fffffff;

    for (int base = 0; base < N_NODES; base += TC) {
        const int cnt = min(TC, N_NODES - base);
        __syncthreads();
        {
            const float4* src4 = (const float4*)(feat + (size_t)base * D_OUT);
            float4* dst4 = (float4*)s_feat;
            const int n4 = (cnt * D_OUT) / 4;
            for (int idx = threadIdx.x; idx < n4; idx += ETPB)
                dst4[idx] = src4[idx];
        }
        for (int idx = threadIdx.x; idx < cnt; idx += ETPB)
            s_sq[idx] = sqn[base + idx];
        __syncthreads();

        if (cnt == TC) {
            // hasq covers BOTH of the warp's queries (adjacent, warp-uniform)
            const bool hasq = (qbase + 1 >= base) && (qbase < base + TC);
            if (hasq) {
                for (int c0 = 0; c0 < TC; c0 += 64)
                    emb_group_p<true>(base, c0, lane, qown, qv, qsq, s_feat, s_sq,
                                      kd, ki, kth_d, kth_i);
            } else {
                for (int c0 = 0; c0 < TC; c0 += 64)
                    emb_group_p<false>(base, c0, lane, qown, qv, qsq, s_feat, s_sq,
                                       kd, ki, kth_d, kth_i);
            }
        } else {
            // tail tile: 16 distinct cands per pass, guarded
            for (int c0 = 0; c0 < cnt; c0 += 16) {
                const int cb = c0 + (lane >> 1);
                const bool bad = (cb >= cnt);
                const int cs = bad ? 0 : cb;
                int j = base + cs;
                const float4* r = (const float4*)&s_feat[cs * D_OUT];
                float a = 0.f;
#pragma unroll
                for (int kk = 0; kk < D_OUT / 4; ++kk) {
                    float4 v = r[kk];
                    a = fmaf(qv[4 * kk + 0], v.x, a);
                    a = fmaf(qv[4 * kk + 1], v.y, a);
                    a = fmaf(qv[4 * kk + 2], v.z, a);
                    a = fmaf(qv[4 * kk + 3], v.w, a);
                }
                float d2v = fmaf(-2.f, a, qsq + s_sq[cs]);
                if (bad || j == qown) { d2v = inf_f(); j = 0x7fffffff; }
                sel1p(d2v, j, lane, kd, ki, kth_d, kth_i);
            }
        }
    }
    // rank r of query (lane&1) lives at lane 2r+(lane&1)
    out_idx[qown * KNN_K + (lane >> 1)] = ki;
}

// ---------------- 5) pos knn: paired queries, 4-cand ILP ----------------
template <bool HASQ>
__device__ __forceinline__ void pos_group_p(
    int base, int c0, int lane, int qown, float4 qp,
    const float4* s_p,
    float& kd, int& ki, float& kth_d, int& kth_i) {
    const int cb = c0 + (lane >> 1);
    const float4 v0 = s_p[cb];
    const float4 v1 = s_p[cb + 16];
    const float4 v2 = s_p[cb + 32];
    const float4 v3 = s_p[cb + 48];
    float a0 = fmaf(qp.x, v0.x, 0.f); a0 = fmaf(qp.y, v0.y, a0); a0 = fmaf(qp.z, v0.z, a0);
    float a1 = fmaf(qp.x, v1.x, 0.f); a1 = fmaf(qp.y, v1.y, a1); a1 = fmaf(qp.z, v1.z, a1);
    float a2 = fmaf(qp.x, v2.x, 0.f); a2 = fmaf(qp.y, v2.y, a2); a2 = fmaf(qp.z, v2.z, a2);
    float a3 = fmaf(qp.x, v3.x, 0.f); a3 = fmaf(qp.y, v3.y, a3); a3 = fmaf(qp.z, v3.z, a3);
    float d0 = __fadd_rn(__fadd_rn(qp.w, v0.w), -__fmul_rn(2.f, a0));
    float d1 = __fadd_rn(__fadd_rn(qp.w, v1.w), -__fmul_rn(2.f, a1));
    float d2 = __fadd_rn(__fadd_rn(qp.w, v2.w), -__fmul_rn(2.f, a2));
    float d3 = __fadd_rn(__fadd_rn(qp.w, v3.w), -__fmul_rn(2.f, a3));
    int j0 = base + cb, j1 = j0 + 16, j2 = j0 + 32, j3 = j0 + 48;
    if (HASQ) {
        if (j0 == qown) { d0 = inf_f(); j0 = 0x7fffffff; }
        if (j1 == qown) { d1 = inf_f(); j1 = 0x7fffffff; }
        if (j2 == qown) { d2 = inf_f(); j2 = 0x7fffffff; }
        if (j3 == qown) { d3 = inf_f(); j3 = 0x7fffffff; }
    }
    sel1p(d0, j0, lane, kd, ki, kth_d, kth_i);
    sel1p(d1, j1, lane, kd, ki, kth_d, kth_i);
    sel1p(d2, j2, lane, kd, ki, kth_d, kth_i);
    sel1p(d3, j3, lane, kd, ki, kth_d, kth_i);
}

__global__ void __launch_bounds__(PTPB) k_knn_pos(const float4* __restrict__ p4,
                                                  int* __restrict__ out_idx) {
    __shared__ float4 s_p[TC];
    const int lane = threadIdx.x & 31;
    const int wid = threadIdx.x >> 5;
    const int qbase = blockIdx.x * PQPB + wid * 2;   // 625*16 == 10000
    const int qown = qbase + (lane & 1);

    const float4 qp = p4[qown];

    float kd = inf_f();  int ki = 0x7fffffff;
    float kth_d = inf_f(); int kth_i = 0x7fffffff;

    for (int base = 0; base < N_NODES; base += TC) {
        const int cnt = min(TC, N_NODES - base);
        __syncthreads();
        for (int idx = threadIdx.x; idx < cnt; idx += PTPB)
            s_p[idx] = p4[base + idx];
        __syncthreads();

        if (cnt == TC) {
            const bool hasq = (qbase + 1 >= base) && (qbase < base + TC);
            if (hasq) {
                for (int c0 = 0; c0 < TC; c0 += 64)
                    pos_group_p<true>(base, c0, lane, qown, qp, s_p, kd, ki, kth_d, kth_i);
            } else {
                for (int c0 = 0; c0 < TC; c0 += 64)
                    pos_group_p<false>(base, c0, lane, qown, qp, s_p, kd, ki, kth_d, kth_i);
            }
        } else {
            for (int c0 = 0; c0 < cnt; c0 += 16) {
                const int cb = c0 + (lane >> 1);
                const bool bad = (cb >= cnt);
                const int cs = bad ? 0 : cb;
                int j = base + cs;
                const float4 v = s_p[cs];
                float a = fmaf(qp.x, v.x, 0.f);
                a = fmaf(qp.y, v.y, a);
                a = fmaf(qp.z, v.z, a);
                float d2v = __fadd_rn(__fadd_rn(qp.w, v.w), -__fmul_rn(2.f, a));
                if (bad || j == qown) { d2v = inf_f(); j = 0x7fffffff; }
                sel1p(d2v, j, lane, kd, ki, kth_d, kth_i);
            }
        }
    }
    out_idx[qown * KNN_K + (lane >> 1)] = ki;
}

// ---------------- 6) epilogue ----------------
__global__ void k_final(const float* __restrict__ tptr, float* __restrict__ out) {
    const int NK = N_NODES * KNN_K;
    int e = blockIdx.x * blockDim.x + threadIdx.x;
    if (e >= NK) return;
    int i = e / KNN_K;
    int src = g_idx_emb[e];
    float s = 0.f;
#pragma unroll
    for (int d = 0; d < D_OUT; ++d) {
        float df = g_embn[src * D_OUT + d] - g_embn[i * D_OUT + d];
        s = fmaf(df, df, s);
    }
    float dist = sqrtf(s);
    float p = expf(-tptr[0] * dist);
    float fi = (float)i;
    float fs = (float)src;

    out[e] = p;
    out[NK + e] = p;
    out[2 * NK + e] = fi;
    out[3 * NK + e] = fs;
    out[4 * NK + e] = fi;
    out[5 * NK + e] = fs;
    out[6 * NK + e] = (float)g_idx_pos[e];
    out[7 * NK + e] = fi;
    out[8 * NK + e] = fi;
}

// ---------------- launch ----------------
extern "C" void kernel_launch(void* const* d_in, const int* in_sizes, int n_in,
                              void* d_out, int out_size) {
    const float* x     = (const float*)d_in[0];
    const float* pos   = (const float*)d_in[1];
    const float* noise = (const float*)d_in[2];
    const float* W     = (const float*)d_in[3];
    const float* b     = (const float*)d_in[4];
    const float* gamma = (const float*)d_in[5];
    const float* beta  = (const float*)d_in[6];
    const float* t     = (const float*)d_in[7];
    float* out = (float*)d_out;

    int nd = N_NODES * D_OUT;
    k_linear<<<(nd + 255) / 256, 256>>>(x, W, b);
    k_stats<<<D_OUT, 256>>>();
    k_emb_sqn<<<(N_NODES + 255) / 256, 256>>>(noise, gamma, beta, pos);

    int* d_idx_emb; cudaGetSymbolAddress((void**)&d_idx_emb, g_idx_emb);
    int* d_idx_pos; cudaGetSymbolAddress((void**)&d_idx_pos, g_idx_pos);
    float* d_emb;   cudaGetSymbolAddress((void**)&d_emb, g_emb);
    float* d_sqe;   cudaGetSymbolAddress((void**)&d_sqe, g_sqe);
    float4* d_pos4; cudaGetSymbolAddress((void**)&d_pos4, g_pos4);

    k_knn_emb<<<N_NODES / EQPB, ETPB>>>(d_emb, d_sqe, d_idx_emb);   // 4th launch -> profiled
    k_knn_pos<<<N_NODES / PQPB, PTPB>>>(d_pos4, d_idx_pos);

    const int NK = N_NODES * KNN_K;
    k_final<<<(NK + 255) / 256, 256>>>(t, out);
    (void)in_sizes; (void)n_in; (void)out_size;
}

// round 16
// speedup vs baseline: 1.1518x; 1.0044x over previous
#include <cuda_runtime.h>
#include <math.h>

#define N_NODES 10000
#define C_IN 128
#define D_OUT 20
#define KNN_K 16
#define FULLM 0xffffffffu

#define ETPB 256                   // emb knn threads per block
#define EQPB ((ETPB / 32) * 2)     // 16 queries per block (2 per warp)
#define PTPB 512                   // pos knn threads per block
#define PWPB (PTPB / 32)           // 16 queries per block (1 per warp)
#define TC 512                     // candidate tile

// ---------------- scratch (static device globals; no allocs) ----------------
__device__ float g_h[N_NODES * D_OUT];
__device__ float g_emb[N_NODES * D_OUT];
__device__ float g_embn[N_NODES * D_OUT];
__device__ float g_sqe[N_NODES];
__device__ float4 g_pos4[N_NODES];         // {x, y, z, sq}
__device__ float g_mu[D_OUT];
__device__ float g_rinv[D_OUT];
__device__ int   g_idx_emb[N_NODES * KNN_K];
__device__ int   g_idx_pos[N_NODES * KNN_K];

__device__ __forceinline__ float inf_f() { return __int_as_float(0x7f800000); }

// ---------------- 1) linear: h = x @ W + b ----------------
__global__ void k_linear(const float* __restrict__ x, const float* __restrict__ W,
                         const float* __restrict__ b) {
    int t = blockIdx.x * blockDim.x + threadIdx.x;
    if (t >= N_NODES * D_OUT) return;
    int i = t / D_OUT;
    int d = t % D_OUT;
    const float* xr = x + (size_t)i * C_IN;
    float acc = 0.f;
#pragma unroll 8
    for (int c = 0; c < C_IN; ++c) acc = fmaf(xr[c], W[c * D_OUT + d], acc);
    g_h[t] = acc + b[d];
}

// ---------------- 2) batchnorm stats (deterministic) ----------------
__global__ void k_stats() {
    __shared__ float ss[256];
    __shared__ float sq[256];
    int d = blockIdx.x;
    int tid = threadIdx.x;
    float s = 0.f, q = 0.f;
    for (int i = tid; i < N_NODES; i += 256) {
        float v = g_h[i * D_OUT + d];
        s += v;
        q = fmaf(v, v, q);
    }
    ss[tid] = s; sq[tid] = q;
    __syncthreads();
    for (int o = 128; o > 0; o >>= 1) {
        if (tid < o) { ss[tid] += ss[tid + o]; sq[tid] += sq[tid + o]; }
        __syncthreads();
    }
    if (tid == 0) {
        float mu = ss[0] / (float)N_NODES;
        float var = sq[0] / (float)N_NODES - mu * mu;
        g_mu[d] = mu;
        g_rinv[d] = 1.f / sqrtf(var + 1e-5f);
    }
}

// ---------------- 3) fused: emb = relu(bn(h)); embn; sq norms; pos4 ----------------
__global__ void k_emb_sqn(const float* __restrict__ noise, const float* __restrict__ gamma,
                          const float* __restrict__ beta, const float* __restrict__ pos) {
    int i = blockIdx.x * blockDim.x + threadIdx.x;
    if (i >= N_NODES) return;
    float s = 0.f;
#pragma unroll
    for (int d = 0; d < D_OUT; ++d) {
        int t = i * D_OUT + d;
        float e = (g_h[t] - g_mu[d]) * g_rinv[d] * gamma[d] + beta[d];
        e = fmaxf(e, 0.f);
        g_emb[t] = e;
        g_embn[t] = e + noise[t] * 1e-4f;
        s = fmaf(e, e, s);
    }
    g_sqe[i] = s;
    float p0 = pos[i * 3 + 0], p1 = pos[i * 3 + 1], p2 = pos[i * 3 + 2];
    float s0 = __fmul_rn(p0, p0);
    float s1 = __fmul_rn(p1, p1);
    float s2 = __fmul_rn(p2, p2);
    float psq = __fadd_rn(__fadd_rn(s0, s1), s2);
    g_pos4[i] = make_float4(p0, p1, p2, psq);
}

// ---------------- shared ordering ----------------
__device__ __forceinline__ bool lt_pair(float d2a, int ia, float d2b, int ib) {
    return (d2a < d2b) || (d2a == d2b && ia < ib);
}

// ---------------- paired warp-distributed top-k (emb) ----------------
// Warp serves TWO queries: even lanes hold query-0's list, odd lanes query-1's.
// Rank r of query p lives at lane 2r+p; kth = rank 15 at lane 30|p.
__device__ __forceinline__ void warp_hits_pair(unsigned mask, float d2, int jj, int lane,
                                               float& kd, int& ki, float& kth_d, int& kth_i) {
    while (mask) {
        int src = __ffs(mask) - 1;
        mask &= mask - 1;
        float dn = __shfl_sync(FULLM, d2, src);
        int   in = __shfl_sync(FULLM, jj, src);
        int par = src & 1;
        bool p = ((lane & 1) == par) && lt_pair(dn, in, kd, ki);
        unsigned pm = __ballot_sync(FULLM, p);
        if (pm) {
            int pos = __ffs(pm) - 1;
            float kdu = __shfl_up_sync(FULLM, kd, 2);
            int   kiu = __shfl_up_sync(FULLM, ki, 2);
            if (p) {
                kd = (lane == pos) ? dn : kdu;
                ki = (lane == pos) ? in : kiu;
            }
            kth_d = __shfl_sync(FULLM, kd, 30 | (lane & 1));
            kth_i = __shfl_sync(FULLM, ki, 30 | (lane & 1));
        }
    }
}

__device__ __forceinline__ void sel1p(float d2v, int jv, int lane,
                                      float& kd, int& ki, float& kth_d, int& kth_i) {
    unsigned m = __ballot_sync(FULLM, lt_pair(d2v, jv, kth_d, kth_i));
    if (m) warp_hits_pair(m, d2v, jv, lane, kd, ki, kth_d, kth_i);
}

// ---------------- unpaired warp-distributed top-k (pos) ----------------
// lane r holds the r-th smallest; kth at lane 15.
__device__ __forceinline__ void warp_hits(unsigned mask, float d2, int jj, int lane,
                                          float& kd, int& ki, float& kth_d, int& kth_i) {
    while (mask) {
        int src = __ffs(mask) - 1;
        mask &= mask - 1;
        float dn = __shfl_sync(FULLM, d2, src);
        int   in = __shfl_sync(FULLM, jj, src);
        if (lt_pair(dn, in, kth_d, kth_i)) {
            bool p = lt_pair(dn, in, kd, ki);
            unsigned pm = __ballot_sync(FULLM, p);
            int pos = __ffs(pm) - 1;
            float kdu = __shfl_up_sync(FULLM, kd, 1);
            int   kiu = __shfl_up_sync(FULLM, ki, 1);
            if (p) {
                kd = (lane == pos) ? dn : kdu;
                ki = (lane == pos) ? in : kiu;
            }
            kth_d = __shfl_sync(FULLM, kd, 15);
            kth_i = __shfl_sync(FULLM, ki, 15);
        }
    }
}

__device__ __forceinline__ void sel1(float d2v, int jv, int lane,
                                     float& kd, int& ki, float& kth_d, int& kth_i) {
    unsigned m = __ballot_sync(FULLM, lt_pair(d2v, jv, kth_d, kth_i));
    if (m) warp_hits(m, d2v, jv, lane, kd, ki, kth_d, kth_i);
}

// ---------------- 4) emb knn: paired queries, 4-cand ILP ----------------
template <bool HASQ>
__device__ __forceinline__ void emb_group_p(
    int base, int c0, int lane, int qown,
    const float (&qv)[D_OUT], float qsq,
    const float* s_feat, const float* s_sq,
    float& kd, int& ki, float& kth_d, int& kth_i) {
    const int cb = c0 + (lane >> 1);          // 16 distinct cands per 32 lanes
    const float4* r0 = (const float4*)&s_feat[cb * D_OUT];
    const float4* r1 = (const float4*)&s_feat[(cb + 16) * D_OUT];
    const float4* r2 = (const float4*)&s_feat[(cb + 32) * D_OUT];
    const float4* r3 = (const float4*)&s_feat[(cb + 48) * D_OUT];
    float a0 = 0.f, a1 = 0.f, a2 = 0.f, a3 = 0.f;
#pragma unroll
    for (int kk = 0; kk < D_OUT / 4; ++kk) {
        float4 v0 = r0[kk], v1 = r1[kk], v2 = r2[kk], v3 = r3[kk];
        float q0 = qv[4 * kk + 0], q1 = qv[4 * kk + 1];
        float q2 = qv[4 * kk + 2], q3 = qv[4 * kk + 3];
        a0 = fmaf(q0, v0.x, a0); a0 = fmaf(q1, v0.y, a0);
        a0 = fmaf(q2, v0.z, a0); a0 = fmaf(q3, v0.w, a0);
        a1 = fmaf(q0, v1.x, a1); a1 = fmaf(q1, v1.y, a1);
        a1 = fmaf(q2, v1.z, a1); a1 = fmaf(q3, v1.w, a1);
        a2 = fmaf(q0, v2.x, a2); a2 = fmaf(q1, v2.y, a2);
        a2 = fmaf(q2, v2.z, a2); a2 = fmaf(q3, v2.w, a2);
        a3 = fmaf(q0, v3.x, a3); a3 = fmaf(q1, v3.y, a3);
        a3 = fmaf(q2, v3.z, a3); a3 = fmaf(q3, v3.w, a3);
    }
    int j0 = base + cb, j1 = j0 + 16, j2 = j0 + 32, j3 = j0 + 48;
    float d0 = fmaf(-2.f, a0, qsq + s_sq[cb]);
    float d1 = fmaf(-2.f, a1, qsq + s_sq[cb + 16]);
    float d2 = fmaf(-2.f, a2, qsq + s_sq[cb + 32]);
    float d3 = fmaf(-2.f, a3, qsq + s_sq[cb + 48]);
    if (HASQ) {
        if (j0 == qown) { d0 = inf_f(); j0 = 0x7fffffff; }
        if (j1 == qown) { d1 = inf_f(); j1 = 0x7fffffff; }
        if (j2 == qown) { d2 = inf_f(); j2 = 0x7fffffff; }
        if (j3 == qown) { d3 = inf_f(); j3 = 0x7fffffff; }
    }
    sel1p(d0, j0, lane, kd, ki, kth_d, kth_i);
    sel1p(d1, j1, lane, kd, ki, kth_d, kth_i);
    sel1p(d2, j2, lane, kd, ki, kth_d, kth_i);
    sel1p(d3, j3, lane, kd, ki, kth_d, kth_i);
}

__global__ void __launch_bounds__(ETPB, 4) k_knn_emb(const float* __restrict__ feat,
                                                     const float* __restrict__ sqn,
                                                     int* __restrict__ out_idx) {
    __shared__ float s_feat[TC * D_OUT];   // 40 KB dense
    __shared__ float s_sq[TC];
    const int lane = threadIdx.x & 31;
    const int wid = threadIdx.x >> 5;
    const int qbase = blockIdx.x * EQPB + wid * 2;   // 625*16 == 10000
    const int qown = qbase + (lane & 1);             // this lane's query

    float qv[D_OUT];
#pragma unroll
    for (int d = 0; d < D_OUT; ++d) qv[d] = feat[(size_t)qown * D_OUT + d];
    const float qsq = sqn[qown];

    float kd = inf_f();  int ki = 0x7fffffff;
    float kth_d = inf_f(); int kth_i = 0x7fffffff;

    for (int base = 0; base < N_NODES; base += TC) {
        const int cnt = min(TC, N_NODES - base);
        __syncthreads();
        {
            const float4* src4 = (const float4*)(feat + (size_t)base * D_OUT);
            float4* dst4 = (float4*)s_feat;
            const int n4 = (cnt * D_OUT) / 4;
            for (int idx = threadIdx.x; idx < n4; idx += ETPB)
                dst4[idx] = src4[idx];
        }
        for (int idx = threadIdx.x; idx < cnt; idx += ETPB)
            s_sq[idx] = sqn[base + idx];
        __syncthreads();

        if (cnt == TC) {
            const bool hasq = (qbase + 1 >= base) && (qbase < base + TC);
            if (hasq) {
                for (int c0 = 0; c0 < TC; c0 += 64)
                    emb_group_p<true>(base, c0, lane, qown, qv, qsq, s_feat, s_sq,
                                      kd, ki, kth_d, kth_i);
            } else {
                for (int c0 = 0; c0 < TC; c0 += 64)
                    emb_group_p<false>(base, c0, lane, qown, qv, qsq, s_feat, s_sq,
                                       kd, ki, kth_d, kth_i);
            }
        } else {
            for (int c0 = 0; c0 < cnt; c0 += 16) {
                const int cb = c0 + (lane >> 1);
                const bool bad = (cb >= cnt);
                const int cs = bad ? 0 : cb;
                int j = base + cs;
                const float4* r = (const float4*)&s_feat[cs * D_OUT];
                float a = 0.f;
#pragma unroll
                for (int kk = 0; kk < D_OUT / 4; ++kk) {
                    float4 v = r[kk];
                    a = fmaf(qv[4 * kk + 0], v.x, a);
                    a = fmaf(qv[4 * kk + 1], v.y, a);
                    a = fmaf(qv[4 * kk + 2], v.z, a);
                    a = fmaf(qv[4 * kk + 3], v.w, a);
                }
                float d2v = fmaf(-2.f, a, qsq + s_sq[cs]);
                if (bad || j == qown) { d2v = inf_f(); j = 0x7fffffff; }
                sel1p(d2v, j, lane, kd, ki, kth_d, kth_i);
            }
        }
    }
    out_idx[qown * KNN_K + (lane >> 1)] = ki;
}

// ---------------- 5) pos knn: unpaired (R10 structure), 4-cand ILP ----------------
template <bool HASQ>
__device__ __forceinline__ void pos_group(
    int base, int c0, int lane, int q, float4 qp,
    const float4* s_p,
    float& kd, int& ki, float& kth_d, int& kth_i) {
    const int ca = c0 + lane;
    const float4 v0 = s_p[ca];
    const float4 v1 = s_p[ca + 32];
    const float4 v2 = s_p[ca + 64];
    const float4 v3 = s_p[ca + 96];
    float a0 = fmaf(qp.x, v0.x, 0.f); a0 = fmaf(qp.y, v0.y, a0); a0 = fmaf(qp.z, v0.z, a0);
    float a1 = fmaf(qp.x, v1.x, 0.f); a1 = fmaf(qp.y, v1.y, a1); a1 = fmaf(qp.z, v1.z, a1);
    float a2 = fmaf(qp.x, v2.x, 0.f); a2 = fmaf(qp.y, v2.y, a2); a2 = fmaf(qp.z, v2.z, a2);
    float a3 = fmaf(qp.x, v3.x, 0.f); a3 = fmaf(qp.y, v3.y, a3); a3 = fmaf(qp.z, v3.z, a3);
    float d0 = __fadd_rn(__fadd_rn(qp.w, v0.w), -__fmul_rn(2.f, a0));
    float d1 = __fadd_rn(__fadd_rn(qp.w, v1.w), -__fmul_rn(2.f, a1));
    float d2 = __fadd_rn(__fadd_rn(qp.w, v2.w), -__fmul_rn(2.f, a2));
    float d3 = __fadd_rn(__fadd_rn(qp.w, v3.w), -__fmul_rn(2.f, a3));
    int j0 = base + ca, j1 = j0 + 32, j2 = j0 + 64, j3 = j0 + 96;
    if (HASQ) {
        if (j0 == q) { d0 = inf_f(); j0 = 0x7fffffff; }
        if (j1 == q) { d1 = inf_f(); j1 = 0x7fffffff; }
        if (j2 == q) { d2 = inf_f(); j2 = 0x7fffffff; }
        if (j3 == q) { d3 = inf_f(); j3 = 0x7fffffff; }
    }
    sel1(d0, j0, lane, kd, ki, kth_d, kth_i);
    sel1(d1, j1, lane, kd, ki, kth_d, kth_i);
    sel1(d2, j2, lane, kd, ki, kth_d, kth_i);
    sel1(d3, j3, lane, kd, ki, kth_d, kth_i);
}

__global__ void __launch_bounds__(PTPB) k_knn_pos(const float4* __restrict__ p4,
                                                  int* __restrict__ out_idx) {
    __shared__ float4 s_p[TC];
    const int lane = threadIdx.x & 31;
    const int wid = threadIdx.x >> 5;
    const int q = blockIdx.x * PWPB + wid;   // 625*16 == 10000

    const float4 qp = p4[q];

    float kd = inf_f();  int ki = 0x7fffffff;
    float kth_d = inf_f(); int kth_i = 0x7fffffff;

    for (int base = 0; base < N_NODES; base += TC) {
        const int cnt = min(TC, N_NODES - base);
        __syncthreads();
        for (int idx = threadIdx.x; idx < cnt; idx += PTPB)
            s_p[idx] = p4[base + idx];
        __syncthreads();

        if (cnt == TC) {
            const bool hasq = (q >= base) && (q < base + TC);
            if (hasq) {
                for (int c0 = 0; c0 < TC; c0 += 128)
                    pos_group<true>(base, c0, lane, q, qp, s_p, kd, ki, kth_d, kth_i);
            } else {
                for (int c0 = 0; c0 < TC; c0 += 128)
                    pos_group<false>(base, c0, lane, q, qp, s_p, kd, ki, kth_d, kth_i);
            }
        } else {
            for (int c0 = 0; c0 < cnt; c0 += 32) {
                const int ca = c0 + lane;
                const bool bad = (ca >= cnt);
                const int cs = bad ? 0 : ca;
                int j = base + cs;
                const float4 v = s_p[cs];
                float a = fmaf(qp.x, v.x, 0.f);
                a = fmaf(qp.y, v.y, a);
                a = fmaf(qp.z, v.z, a);
                float d2v = __fadd_rn(__fadd_rn(qp.w, v.w), -__fmul_rn(2.f, a));
                if (bad || j == q) { d2v = inf_f(); j = 0x7fffffff; }
                sel1(d2v, j, lane, kd, ki, kth_d, kth_i);
            }
        }
    }
    if (lane < KNN_K) out_idx[q * KNN_K + lane] = ki;
}

// ---------------- 6) epilogue ----------------
__global__ void k_final(const float* __restrict__ tptr, float* __restrict__ out) {
    const int NK = N_NODES * KNN_K;
    int e = blockIdx.x * blockDim.x + threadIdx.x;
    if (e >= NK) return;
    int i = e / KNN_K;
    int src = g_idx_emb[e];
    float s = 0.f;
#pragma unroll
    for (int d = 0; d < D_OUT; ++d) {
        float df = g_embn[src * D_OUT + d] - g_embn[i * D_OUT + d];
        s = fmaf(df, df, s);
    }
    float dist = sqrtf(s);
    float p = expf(-tptr[0] * dist);
    float fi = (float)i;
    float fs = (float)src;

    out[e] = p;
    out[NK + e] = p;
    out[2 * NK + e] = fi;
    out[3 * NK + e] = fs;
    out[4 * NK + e] = fi;
    out[5 * NK + e] = fs;
    out[6 * NK + e] = (float)g_idx_pos[e];
    out[7 * NK + e] = fi;
    out[8 * NK + e] = fi;
}

// ---------------- launch ----------------
extern "C" void kernel_launch(void* const* d_in, const int* in_sizes, int n_in,
                              void* d_out, int out_size) {
    const float* x     = (const float*)d_in[0];
    const float* pos   = (const float*)d_in[1];
    const float* noise = (const float*)d_in[2];
    const float* W     = (const float*)d_in[3];
    const float* b     = (const float*)d_in[4];
    const float* gamma = (const float*)d_in[5];
    const float* beta  = (const float*)d_in[6];
    const float* t     = (const float*)d_in[7];
    float* out = (float*)d_out;

    int nd = N_NODES * D_OUT;
    k_linear<<<(nd + 255) / 256, 256>>>(x, W, b);
    k_stats<<<D_OUT, 256>>>();
    k_emb_sqn<<<(N_NODES + 255) / 256, 256>>>(noise, gamma, beta, pos);

    int* d_idx_emb; cudaGetSymbolAddress((void**)&d_idx_emb, g_idx_emb);
    int* d_idx_pos; cudaGetSymbolAddress((void**)&d_idx_pos, g_idx_pos);
    float* d_emb;   cudaGetSymbolAddress((void**)&d_emb, g_emb);
    float* d_sqe;   cudaGetSymbolAddress((void**)&d_sqe, g_sqe);
    float4* d_pos4; cudaGetSymbolAddress((void**)&d_pos4, g_pos4);

    k_knn_emb<<<N_NODES / EQPB, ETPB>>>(d_emb, d_sqe, d_idx_emb);   // 4th launch -> profiled
    k_knn_pos<<<N_NODES / PWPB, PTPB>>>(d_pos4, d_idx_pos);

    const int NK = N_NODES * KNN_K;
    k_final<<<(NK + 255) / 256, 256>>>(t, out);
    (void)in_sizes; (void)n_in; (void)out_size;
}

// round 17
// speedup vs baseline: 1.3554x; 1.1768x over previous
#include <cuda_runtime.h>
#include <math.h>

#define N_NODES 10000
#define C_IN 128
#define D_OUT 20
#define KNN_K 16
#define FULLM 0xffffffffu

#define KTPB 256                   // fused knn threads per block
#define EQPB 16                    // emb: 16 queries per block (2 per warp, 8 warps)
#define PQPB 8                     // pos: 8 queries per block (1 per warp)
#define EGRID (N_NODES / EQPB)     // 625 emb blocks
#define PGRID (N_NODES / PQPB)     // 1250 pos blocks
#define TC 512                     // candidate tile
#define SMEM_FLOATS (TC * D_OUT + TC)   // 10752 floats = 42 KB (union)

// ---------------- scratch (static device globals; no allocs) ----------------
__device__ float g_h[N_NODES * D_OUT];
__device__ float g_emb[N_NODES * D_OUT];
__device__ float g_embn[N_NODES * D_OUT];
__device__ float g_sqe[N_NODES];
__device__ float4 g_pos4[N_NODES];         // {x, y, z, sq}
__device__ float g_mu[D_OUT];
__device__ float g_rinv[D_OUT];
__device__ int   g_idx_emb[N_NODES * KNN_K];
__device__ int   g_idx_pos[N_NODES * KNN_K];

__device__ __forceinline__ float inf_f() { return __int_as_float(0x7f800000); }

// ---------------- 1) linear: h = x @ W + b ----------------
__global__ void k_linear(const float* __restrict__ x, const float* __restrict__ W,
                         const float* __restrict__ b) {
    int t = blockIdx.x * blockDim.x + threadIdx.x;
    if (t >= N_NODES * D_OUT) return;
    int i = t / D_OUT;
    int d = t % D_OUT;
    const float* xr = x + (size_t)i * C_IN;
    float acc = 0.f;
#pragma unroll 8
    for (int c = 0; c < C_IN; ++c) acc = fmaf(xr[c], W[c * D_OUT + d], acc);
    g_h[t] = acc + b[d];
}

// ---------------- 2) batchnorm stats (deterministic) ----------------
__global__ void k_stats() {
    __shared__ float ss[256];
    __shared__ float sq[256];
    int d = blockIdx.x;
    int tid = threadIdx.x;
    float s = 0.f, q = 0.f;
    for (int i = tid; i < N_NODES; i += 256) {
        float v = g_h[i * D_OUT + d];
        s += v;
        q = fmaf(v, v, q);
    }
    ss[tid] = s; sq[tid] = q;
    __syncthreads();
    for (int o = 128; o > 0; o >>= 1) {
        if (tid < o) { ss[tid] += ss[tid + o]; sq[tid] += sq[tid + o]; }
        __syncthreads();
    }
    if (tid == 0) {
        float mu = ss[0] / (float)N_NODES;
        float var = sq[0] / (float)N_NODES - mu * mu;
        g_mu[d] = mu;
        g_rinv[d] = 1.f / sqrtf(var + 1e-5f);
    }
}

// ---------------- 3) fused: emb = relu(bn(h)); embn; sq norms; pos4 ----------------
__global__ void k_emb_sqn(const float* __restrict__ noise, const float* __restrict__ gamma,
                          const float* __restrict__ beta, const float* __restrict__ pos) {
    int i = blockIdx.x * blockDim.x + threadIdx.x;
    if (i >= N_NODES) return;
    float s = 0.f;
#pragma unroll
    for (int d = 0; d < D_OUT; ++d) {
        int t = i * D_OUT + d;
        float e = (g_h[t] - g_mu[d]) * g_rinv[d] * gamma[d] + beta[d];
        e = fmaxf(e, 0.f);
        g_emb[t] = e;
        g_embn[t] = e + noise[t] * 1e-4f;
        s = fmaf(e, e, s);
    }
    g_sqe[i] = s;
    float p0 = pos[i * 3 + 0], p1 = pos[i * 3 + 1], p2 = pos[i * 3 + 2];
    float s0 = __fmul_rn(p0, p0);
    float s1 = __fmul_rn(p1, p1);
    float s2 = __fmul_rn(p2, p2);
    float psq = __fadd_rn(__fadd_rn(s0, s1), s2);
    g_pos4[i] = make_float4(p0, p1, p2, psq);
}

// ---------------- shared ordering ----------------
__device__ __forceinline__ bool lt_pair(float d2a, int ia, float d2b, int ib) {
    return (d2a < d2b) || (d2a == d2b && ia < ib);
}

// ---------------- paired warp-distributed top-k (emb) ----------------
__device__ __forceinline__ void warp_hits_pair(unsigned mask, float d2, int jj, int lane,
                                               float& kd, int& ki, float& kth_d, int& kth_i) {
    while (mask) {
        int src = __ffs(mask) - 1;
        mask &= mask - 1;
        float dn = __shfl_sync(FULLM, d2, src);
        int   in = __shfl_sync(FULLM, jj, src);
        int par = src & 1;
        bool p = ((lane & 1) == par) && lt_pair(dn, in, kd, ki);
        unsigned pm = __ballot_sync(FULLM, p);
        if (pm) {
            int pos = __ffs(pm) - 1;
            float kdu = __shfl_up_sync(FULLM, kd, 2);
            int   kiu = __shfl_up_sync(FULLM, ki, 2);
            if (p) {
                kd = (lane == pos) ? dn : kdu;
                ki = (lane == pos) ? in : kiu;
            }
            kth_d = __shfl_sync(FULLM, kd, 30 | (lane & 1));
            kth_i = __shfl_sync(FULLM, ki, 30 | (lane & 1));
        }
    }
}

__device__ __forceinline__ void sel1p(float d2v, int jv, int lane,
                                      float& kd, int& ki, float& kth_d, int& kth_i) {
    unsigned m = __ballot_sync(FULLM, lt_pair(d2v, jv, kth_d, kth_i));
    if (m) warp_hits_pair(m, d2v, jv, lane, kd, ki, kth_d, kth_i);
}

// ---------------- unpaired warp-distributed top-k (pos) ----------------
__device__ __forceinline__ void warp_hits(unsigned mask, float d2, int jj, int lane,
                                          float& kd, int& ki, float& kth_d, int& kth_i) {
    while (mask) {
        int src = __ffs(mask) - 1;
        mask &= mask - 1;
        float dn = __shfl_sync(FULLM, d2, src);
        int   in = __shfl_sync(FULLM, jj, src);
        if (lt_pair(dn, in, kth_d, kth_i)) {
            bool p = lt_pair(dn, in, kd, ki);
            unsigned pm = __ballot_sync(FULLM, p);
            int pos = __ffs(pm) - 1;
            float kdu = __shfl_up_sync(FULLM, kd, 1);
            int   kiu = __shfl_up_sync(FULLM, ki, 1);
            if (p) {
                kd = (lane == pos) ? dn : kdu;
                ki = (lane == pos) ? in : kiu;
            }
            kth_d = __shfl_sync(FULLM, kd, 15);
            kth_i = __shfl_sync(FULLM, ki, 15);
        }
    }
}

__device__ __forceinline__ void sel1(float d2v, int jv, int lane,
                                     float& kd, int& ki, float& kth_d, int& kth_i) {
    unsigned m = __ballot_sync(FULLM, lt_pair(d2v, jv, kth_d, kth_i));
    if (m) warp_hits(m, d2v, jv, lane, kd, ki, kth_d, kth_i);
}

// ---------------- emb role: paired queries, 4-cand ILP ----------------
template <bool HASQ>
__device__ __forceinline__ void emb_group_p(
    int base, int c0, int lane, int qown,
    const float (&qv)[D_OUT], float qsq,
    const float* s_feat, const float* s_sq,
    float& kd, int& ki, float& kth_d, int& kth_i) {
    const int cb = c0 + (lane >> 1);
    const float4* r0 = (const float4*)&s_feat[cb * D_OUT];
    const float4* r1 = (const float4*)&s_feat[(cb + 16) * D_OUT];
    const float4* r2 = (const float4*)&s_feat[(cb + 32) * D_OUT];
    const float4* r3 = (const float4*)&s_feat[(cb + 48) * D_OUT];
    float a0 = 0.f, a1 = 0.f, a2 = 0.f, a3 = 0.f;
#pragma unroll
    for (int kk = 0; kk < D_OUT / 4; ++kk) {
        float4 v0 = r0[kk], v1 = r1[kk], v2 = r2[kk], v3 = r3[kk];
        float q0 = qv[4 * kk + 0], q1 = qv[4 * kk + 1];
        float q2 = qv[4 * kk + 2], q3 = qv[4 * kk + 3];
        a0 = fmaf(q0, v0.x, a0); a0 = fmaf(q1, v0.y, a0);
        a0 = fmaf(q2, v0.z, a0); a0 = fmaf(q3, v0.w, a0);
        a1 = fmaf(q0, v1.x, a1); a1 = fmaf(q1, v1.y, a1);
        a1 = fmaf(q2, v1.z, a1); a1 = fmaf(q3, v1.w, a1);
        a2 = fmaf(q0, v2.x, a2); a2 = fmaf(q1, v2.y, a2);
        a2 = fmaf(q2, v2.z, a2); a2 = fmaf(q3, v2.w, a2);
        a3 = fmaf(q0, v3.x, a3); a3 = fmaf(q1, v3.y, a3);
        a3 = fmaf(q2, v3.z, a3); a3 = fmaf(q3, v3.w, a3);
    }
    int j0 = base + cb, j1 = j0 + 16, j2 = j0 + 32, j3 = j0 + 48;
    float d0 = fmaf(-2.f, a0, qsq + s_sq[cb]);
    float d1 = fmaf(-2.f, a1, qsq + s_sq[cb + 16]);
    float d2 = fmaf(-2.f, a2, qsq + s_sq[cb + 32]);
    float d3 = fmaf(-2.f, a3, qsq + s_sq[cb + 48]);
    if (HASQ) {
        if (j0 == qown) { d0 = inf_f(); j0 = 0x7fffffff; }
        if (j1 == qown) { d1 = inf_f(); j1 = 0x7fffffff; }
        if (j2 == qown) { d2 = inf_f(); j2 = 0x7fffffff; }
        if (j3 == qown) { d3 = inf_f(); j3 = 0x7fffffff; }
    }
    sel1p(d0, j0, lane, kd, ki, kth_d, kth_i);
    sel1p(d1, j1, lane, kd, ki, kth_d, kth_i);
    sel1p(d2, j2, lane, kd, ki, kth_d, kth_i);
    sel1p(d3, j3, lane, kd, ki, kth_d, kth_i);
}

__device__ void knn_emb_role(int bid, int tid, const float* feat, const float* sqn,
                             int* out_idx, float* s_mem) {
    float* s_feat = s_mem;
    float* s_sq = s_mem + TC * D_OUT;
    const int lane = tid & 31;
    const int wid = tid >> 5;
    const int qbase = bid * EQPB + wid * 2;
    const int qown = qbase + (lane & 1);

    float qv[D_OUT];
#pragma unroll
    for (int d = 0; d < D_OUT; ++d) qv[d] = feat[(size_t)qown * D_OUT + d];
    const float qsq = sqn[qown];

    float kd = inf_f();  int ki = 0x7fffffff;
    float kth_d = inf_f(); int kth_i = 0x7fffffff;

    for (int base = 0; base < N_NODES; base += TC) {
        const int cnt = min(TC, N_NODES - base);
        __syncthreads();
        {
            const float4* src4 = (const float4*)(feat + (size_t)base * D_OUT);
            float4* dst4 = (float4*)s_feat;
            const int n4 = (cnt * D_OUT) / 4;
            for (int idx = tid; idx < n4; idx += KTPB)
                dst4[idx] = src4[idx];
        }
        for (int idx = tid; idx < cnt; idx += KTPB)
            s_sq[idx] = sqn[base + idx];
        __syncthreads();

        if (cnt == TC) {
            const bool hasq = (qbase + 1 >= base) && (qbase < base + TC);
            if (hasq) {
                for (int c0 = 0; c0 < TC; c0 += 64)
                    emb_group_p<true>(base, c0, lane, qown, qv, qsq, s_feat, s_sq,
                                      kd, ki, kth_d, kth_i);
            } else {
                for (int c0 = 0; c0 < TC; c0 += 64)
                    emb_group_p<false>(base, c0, lane, qown, qv, qsq, s_feat, s_sq,
                                       kd, ki, kth_d, kth_i);
            }
        } else {
            for (int c0 = 0; c0 < cnt; c0 += 16) {
                const int cb = c0 + (lane >> 1);
                const bool bad = (cb >= cnt);
                const int cs = bad ? 0 : cb;
                int j = base + cs;
                const float4* r = (const float4*)&s_feat[cs * D_OUT];
                float a = 0.f;
#pragma unroll
                for (int kk = 0; kk < D_OUT / 4; ++kk) {
                    float4 v = r[kk];
                    a = fmaf(qv[4 * kk + 0], v.x, a);
                    a = fmaf(qv[4 * kk + 1], v.y, a);
                    a = fmaf(qv[4 * kk + 2], v.z, a);
                    a = fmaf(qv[4 * kk + 3], v.w, a);
                }
                float d2v = fmaf(-2.f, a, qsq + s_sq[cs]);
                if (bad || j == qown) { d2v = inf_f(); j = 0x7fffffff; }
                sel1p(d2v, j, lane, kd, ki, kth_d, kth_i);
            }
        }
    }
    out_idx[qown * KNN_K + (lane >> 1)] = ki;
}

// ---------------- pos role: unpaired, 4-cand ILP ----------------
template <bool HASQ>
__device__ __forceinline__ void pos_group(
    int base, int c0, int lane, int q, float4 qp,
    const float4* s_p,
    float& kd, int& ki, float& kth_d, int& kth_i) {
    const int ca = c0 + lane;
    const float4 v0 = s_p[ca];
    const float4 v1 = s_p[ca + 32];
    const float4 v2 = s_p[ca + 64];
    const float4 v3 = s_p[ca + 96];
    float a0 = fmaf(qp.x, v0.x, 0.f); a0 = fmaf(qp.y, v0.y, a0); a0 = fmaf(qp.z, v0.z, a0);
    float a1 = fmaf(qp.x, v1.x, 0.f); a1 = fmaf(qp.y, v1.y, a1); a1 = fmaf(qp.z, v1.z, a1);
    float a2 = fmaf(qp.x, v2.x, 0.f); a2 = fmaf(qp.y, v2.y, a2); a2 = fmaf(qp.z, v2.z, a2);
    float a3 = fmaf(qp.x, v3.x, 0.f); a3 = fmaf(qp.y, v3.y, a3); a3 = fmaf(qp.z, v3.z, a3);
    float d0 = __fadd_rn(__fadd_rn(qp.w, v0.w), -__fmul_rn(2.f, a0));
    float d1 = __fadd_rn(__fadd_rn(qp.w, v1.w), -__fmul_rn(2.f, a1));
    float d2 = __fadd_rn(__fadd_rn(qp.w, v2.w), -__fmul_rn(2.f, a2));
    float d3 = __fadd_rn(__fadd_rn(qp.w, v3.w), -__fmul_rn(2.f, a3));
    int j0 = base + ca, j1 = j0 + 32, j2 = j0 + 64, j3 = j0 + 96;
    if (HASQ) {
        if (j0 == q) { d0 = inf_f(); j0 = 0x7fffffff; }
        if (j1 == q) { d1 = inf_f(); j1 = 0x7fffffff; }
        if (j2 == q) { d2 = inf_f(); j2 = 0x7fffffff; }
        if (j3 == q) { d3 = inf_f(); j3 = 0x7fffffff; }
    }
    sel1(d0, j0, lane, kd, ki, kth_d, kth_i);
    sel1(d1, j1, lane, kd, ki, kth_d, kth_i);
    sel1(d2, j2, lane, kd, ki, kth_d, kth_i);
    sel1(d3, j3, lane, kd, ki, kth_d, kth_i);
}

__device__ void knn_pos_role(int bid, int tid, const float4* p4,
                             int* out_idx, float* s_mem) {
    float4* s_p = (float4*)s_mem;
    const int lane = tid & 31;
    const int wid = tid >> 5;
    const int q = bid * PQPB + wid;

    const float4 qp = p4[q];

    float kd = inf_f();  int ki = 0x7fffffff;
    float kth_d = inf_f(); int kth_i = 0x7fffffff;

    for (int base = 0; base < N_NODES; base += TC) {
        const int cnt = min(TC, N_NODES - base);
        __syncthreads();
        for (int idx = tid; idx < cnt; idx += KTPB)
            s_p[idx] = p4[base + idx];
        __syncthreads();

        if (cnt == TC) {
            const bool hasq = (q >= base) && (q < base + TC);
            if (hasq) {
                for (int c0 = 0; c0 < TC; c0 += 128)
                    pos_group<true>(base, c0, lane, q, qp, s_p, kd, ki, kth_d, kth_i);
            } else {
                for (int c0 = 0; c0 < TC; c0 += 128)
                    pos_group<false>(base, c0, lane, q, qp, s_p, kd, ki, kth_d, kth_i);
            }
        } else {
            for (int c0 = 0; c0 < cnt; c0 += 32) {
                const int ca = c0 + lane;
                const bool bad = (ca >= cnt);
                const int cs = bad ? 0 : ca;
                int j = base + cs;
                const float4 v = s_p[cs];
                float a = fmaf(qp.x, v.x, 0.f);
                a = fmaf(qp.y, v.y, a);
                a = fmaf(qp.z, v.z, a);
                float d2v = __fadd_rn(__fadd_rn(qp.w, v.w), -__fmul_rn(2.f, a));
                if (bad || j == q) { d2v = inf_f(); j = 0x7fffffff; }
                sel1(d2v, j, lane, kd, ki, kth_d, kth_i);
            }
        }
    }
    if (lane < KNN_K) out_idx[q * KNN_K + lane] = ki;
}

// ---------------- 4) fused knn: emb blocks then pos blocks, one launch ----------------
__global__ void __launch_bounds__(KTPB) k_knn_fused(const float* __restrict__ feat,
                                                    const float* __restrict__ sqn,
                                                    const float4* __restrict__ p4,
                                                    int* __restrict__ out_emb,
                                                    int* __restrict__ out_pos) {
    __shared__ __align__(16) float s_mem[SMEM_FLOATS];
    if (blockIdx.x < EGRID)
        knn_emb_role(blockIdx.x, threadIdx.x, feat, sqn, out_emb, s_mem);
    else
        knn_pos_role(blockIdx.x - EGRID, threadIdx.x, p4, out_pos, s_mem);
}

// ---------------- 5) epilogue ----------------
__global__ void k_final(const float* __restrict__ tptr, float* __restrict__ out) {
    const int NK = N_NODES * KNN_K;
    int e = blockIdx.x * blockDim.x + threadIdx.x;
    if (e >= NK) return;
    int i = e / KNN_K;
    int src = g_idx_emb[e];
    float s = 0.f;
#pragma unroll
    for (int d = 0; d < D_OUT; ++d) {
        float df = g_embn[src * D_OUT + d] - g_embn[i * D_OUT + d];
        s = fmaf(df, df, s);
    }
    float dist = sqrtf(s);
    float p = expf(-tptr[0] * dist);
    float fi = (float)i;
    float fs = (float)src;

    out[e] = p;
    out[NK + e] = p;
    out[2 * NK + e] = fi;
    out[3 * NK + e] = fs;
    out[4 * NK + e] = fi;
    out[5 * NK + e] = fs;
    out[6 * NK + e] = (float)g_idx_pos[e];
    out[7 * NK + e] = fi;
    out[8 * NK + e] = fi;
}

// ---------------- launch ----------------
extern "C" void kernel_launch(void* const* d_in, const int* in_sizes, int n_in,
                              void* d_out, int out_size) {
    const float* x     = (const float*)d_in[0];
    const float* pos   = (const float*)d_in[1];
    const float* noise = (const float*)d_in[2];
    const float* W     = (const float*)d_in[3];
    const float* b     = (const float*)d_in[4];
    const float* gamma = (const float*)d_in[5];
    const float* beta  = (const float*)d_in[6];
    const float* t     = (const float*)d_in[7];
    float* out = (float*)d_out;

    int nd = N_NODES * D_OUT;
    k_linear<<<(nd + 255) / 256, 256>>>(x, W, b);
    k_stats<<<D_OUT, 256>>>();
    k_emb_sqn<<<(N_NODES + 255) / 256, 256>>>(noise, gamma, beta, pos);

    int* d_idx_emb; cudaGetSymbolAddress((void**)&d_idx_emb, g_idx_emb);
    int* d_idx_pos; cudaGetSymbolAddress((void**)&d_idx_pos, g_idx_pos);
    float* d_emb;   cudaGetSymbolAddress((void**)&d_emb, g_emb);
    float* d_sqe;   cudaGetSymbolAddress((void**)&d_sqe, g_sqe);
    float4* d_pos4; cudaGetSymbolAddress((void**)&d_pos4, g_pos4);

    k_knn_fused<<<EGRID + PGRID, KTPB>>>(d_emb, d_sqe, d_pos4, d_idx_emb, d_idx_pos);

    const int NK = N_NODES * KNN_K;
    k_final<<<(NK + 255) / 256, 256>>>(t, out);
    (void)in_sizes; (void)n_in; (void)out_size;
}